// round 4
// baseline (speedup 1.0000x reference)
#include <cuda_runtime.h>

#define NQ 12
#define THREADS 256
#define PI_F 3.14159265358979323846f
typedef unsigned long long u64;

// Precomputed (batch-independent) circuit data, written by precompute kernel
__device__ u64      g_G[630];     // packed gate coefficients, layers 1..5
__device__ unsigned g_RM[72];     // CNOT masks: fwd layers 0..4, inverse layer 5
__device__ float2   g_U0[48];     // layer-0 Rot matrices

__device__ __forceinline__ float2 cmul(float2 a, float2 b) {
    return make_float2(a.x * b.x - a.y * b.y, a.x * b.y + a.y * b.x);
}
__device__ __forceinline__ u64 pk2(float a, float b) {
    u64 r; asm("mov.b64 %0,{%1,%2};" : "=l"(r) : "f"(a), "f"(b)); return r;
}
__device__ __forceinline__ void unpk(u64 x, float& a, float& b) {
    asm("mov.b64 {%0,%1},%2;" : "=f"(a), "=f"(b) : "l"(x));
}
__device__ __forceinline__ u64 m2(u64 a, u64 b) {
    u64 d; asm("mul.rn.f32x2 %0,%1,%2;" : "=l"(d) : "l"(a), "l"(b)); return d;
}
__device__ __forceinline__ u64 fma2(u64 a, u64 b, u64 c) {
    u64 d; asm("fma.rn.f32x2 %0,%1,%2,%3;" : "=l"(d) : "l"(a), "l"(b), "l"(c)); return d;
}
__device__ __forceinline__ u64 swp(u64 x) {
    float lo, hi; unpk(x, lo, hi); return pk2(hi, lo);
}

// ---------------------------------------------------------------------------
// Precompute kernel
// ---------------------------------------------------------------------------
__global__ void precompute_kernel(const float* __restrict__ weights) {
    __shared__ float2 U[6][NQ][2][2];
    int tid = threadIdx.x;

    for (int g = tid; g < 6 * NQ; g += blockDim.x) {
        float phi = weights[g * 3 + 0];
        float th  = weights[g * 3 + 1];
        float om  = weights[g * 3 + 2];
        float s = sinf(0.5f * th), c = cosf(0.5f * th);
        float ap = 0.5f * (phi + om), am = 0.5f * (phi - om);
        float sap = sinf(ap), cap = cosf(ap);
        float sam = sinf(am), cam = cosf(am);
        int l = g / NQ, w = g % NQ;
        U[l][w][0][0] = make_float2(cap * c, -sap * c);
        U[l][w][0][1] = make_float2(-cam * s, -sam * s);
        U[l][w][1][0] = make_float2(cam * s, -sam * s);
        U[l][w][1][1] = make_float2(cap * c, sap * c);
    }
    __syncthreads();

    for (int e = tid; e < NQ * 4; e += blockDim.x) {
        int w = e >> 2;
        g_U0[e] = U[0][w][(e >> 1) & 1][e & 1];
    }
    // Packed coefficient blocks: per (layer 1..5, config 0..2): 42 u64
    //  3 broadcast gates (local bits 0..2): 12 u64 each: per entry {(re,re),(-im,-im),(im,im)}
    //  1 packing gate (local bit 3): 6 u64: P1,P2,P3,P4,Q3,Q4
    if (tid < 15) {
        int l = tid / 3 + 1, c = tid % 3;
        int base = (l - 1) * 126 + c * 42;
        for (int bit = 0; bit < 3; bit++) {
            for (int e = 0; e < 4; e++) {
                float2 u = U[l][c * 4 + bit][e >> 1][e & 1];
                int off = base + bit * 12 + e * 3;
                g_G[off + 0] = pk2(u.x, u.x);
                g_G[off + 1] = pk2(-u.y, -u.y);
                g_G[off + 2] = pk2(u.y, u.y);
            }
        }
        float2 u00 = U[l][c * 4 + 3][0][0], u01 = U[l][c * 4 + 3][0][1];
        float2 u10 = U[l][c * 4 + 3][1][0], u11 = U[l][c * 4 + 3][1][1];
        g_G[base + 36] = pk2(u00.x, u11.x);
        g_G[base + 37] = pk2(u01.x, u10.x);
        g_G[base + 38] = pk2(-u00.y, -u11.y);
        g_G[base + 39] = pk2(-u01.y, -u10.y);
        g_G[base + 40] = pk2(u00.y, u11.y);
        g_G[base + 41] = pk2(u01.y, u10.y);
    }
    // CNOT-ring masks: forward for layers 0..4 (read folding), inverse for layer 5.
    for (int e = tid; e < 6 * NQ; e += blockDim.x) {
        int l = e / NQ, bb = e % NQ;
        unsigned i = 1u << bb;
        if (l < 5) {
            int r = (l % (NQ - 1)) + 1;
            for (int w = NQ - 1; w >= 0; --w)
                i ^= ((i >> w) & 1u) << ((w + r) % NQ);
        } else {
            int r = (5 % (NQ - 1)) + 1;
            for (int w = 0; w < NQ; ++w)
                i ^= ((i >> w) & 1u) << ((w + r) % NQ);
        }
        g_RM[l * NQ + bb] = i;
    }
}

// ---------------------------------------------------------------------------
// Gates on SoA packed registers (RE[m],IM[m] pack amp pair (m, m+8))
// ---------------------------------------------------------------------------
template <int Q>
__device__ __forceinline__ void bgate(u64* RE, u64* IM, const u64* __restrict__ g) {
    u64 c00r = g[0], c00n = g[1], c00p = g[2];
    u64 c01r = g[3], c01n = g[4], c01p = g[5];
    u64 c10r = g[6], c10n = g[7], c10p = g[8];
    u64 c11r = g[9], c11n = g[10], c11p = g[11];
#pragma unroll
    for (int h = 0; h < 4; h++) {
        const int a = ((h >> Q) << (Q + 1)) | (h & ((1 << Q) - 1));
        const int bq = a + (1 << Q);
        u64 x0r = RE[a], x0i = IM[a], x1r = RE[bq], x1i = IM[bq];
        u64 y0r = m2(c00r, x0r); y0r = fma2(c00n, x0i, y0r); y0r = fma2(c01r, x1r, y0r); y0r = fma2(c01n, x1i, y0r);
        u64 y0i = m2(c00r, x0i); y0i = fma2(c00p, x0r, y0i); y0i = fma2(c01r, x1i, y0i); y0i = fma2(c01p, x1r, y0i);
        u64 y1r = m2(c10r, x0r); y1r = fma2(c10n, x0i, y1r); y1r = fma2(c11r, x1r, y1r); y1r = fma2(c11n, x1i, y1r);
        u64 y1i = m2(c10r, x0i); y1i = fma2(c10p, x0r, y1i); y1i = fma2(c11r, x1i, y1i); y1i = fma2(c11p, x1r, y1i);
        RE[a] = y0r; IM[a] = y0i; RE[bq] = y1r; IM[bq] = y1i;
    }
}

__device__ __forceinline__ void pgate(u64* RE, u64* IM, const u64* __restrict__ g) {
    u64 P1 = g[0], P2 = g[1], P3 = g[2], P4 = g[3], Q3 = g[4], Q4 = g[5];
#pragma unroll
    for (int m = 0; m < 8; m++) {
        u64 xr = RE[m], xi = IM[m];
        u64 sr = swp(xr), si = swp(xi);
        u64 yr = m2(P1, xr); yr = fma2(P2, sr, yr); yr = fma2(P3, xi, yr); yr = fma2(P4, si, yr);
        u64 yi = m2(P1, xi); yi = fma2(P2, si, yi); yi = fma2(Q3, xr, yi); yi = fma2(Q4, sr, yi);
        RE[m] = yr; IM[m] = yi;
    }
}

// ---------------------------------------------------------------------------
// Main kernel. SMEM SoA, swizzle phi(j) = j ^ ((j>>4)&31).
// Config A: j=(t<<4)|m  Config B: j=(thi<<8)|(m<<4)|tlo  Config C: j=(m<<8)|t
// ---------------------------------------------------------------------------
__global__ void __launch_bounds__(THREADS, 4) qvl_kernel(
    const float* __restrict__ v, const float* __restrict__ W,
    const float* __restrict__ bc, float* __restrict__ out) {
    __shared__ float    Sre[4096];
    __shared__ float    Sim[4096];
    __shared__ u64      sG[630];      // gate coefficients (SMEM: no LDC port floor)
    __shared__ unsigned sT[6][256];   // per-layer scatter-base tables (t bits 0..7)
    __shared__ unsigned sRM[72];      // raw masks (per-m terms)
    __shared__ float2   sAH[40];      // [0..23] per-qubit 2-vecs, [24..39] high product

    int b = blockIdx.x, t = threadIdx.x;
    int lane = t & 31, warp = t >> 5;

    // Stage batch-independent data
#pragma unroll
    for (int e = t; e < 630; e += THREADS) sG[e] = g_G[e];
    if (t < 72) sRM[t] = g_RM[t];

    // Angles: x_w = tanh(v[b]·W[w] + b[w]) * pi, fold layer-0 Rot
    const float* vrow = v + (size_t)b * 512;
    for (int w = warp; w < NQ; w += 8) {
        const float* Wr = W + w * 512;
        float acc = 0.f;
#pragma unroll
        for (int q = 0; q < 16; q++)
            acc = fmaf(vrow[lane + 32 * q], Wr[lane + 32 * q], acc);
#pragma unroll
        for (int o = 16; o; o >>= 1) acc += __shfl_xor_sync(0xFFFFFFFFu, acc, o);
        if (lane == 0) {
            float x = tanhf(acc + bc[w]) * PI_F;
            float ch = cosf(0.5f * x), sh = sinf(0.5f * x);
            float2 u00 = g_U0[w * 4 + 0], u01 = g_U0[w * 4 + 1];
            float2 u10 = g_U0[w * 4 + 2], u11 = g_U0[w * 4 + 3];
            sAH[2 * w + 0] = make_float2(u00.x * ch + u01.x * sh, u00.y * ch + u01.y * sh);
            sAH[2 * w + 1] = make_float2(u10.x * ch + u11.x * sh, u10.y * ch + u11.y * sh);
        }
    }
    __syncthreads();

    // Build scatter-base tables (once per CTA): entry = XOR of masks for set bits of tt.
    // Tables 0..4: layers 1..5 (terms g_RM[l*12+4+k]); table 5: expval inverse (g_RM[60+k]).
#pragma unroll
    for (int e = t; e < 6 * 256; e += THREADS) {
        int l = e >> 8, tt = e & 255;
        int off = l * 12 + (l < 5 ? 4 : 0);
        unsigned mm = 0;
#pragma unroll
        for (int k = 0; k < 8; k++)
            mm ^= sRM[off + k] & (unsigned)(-(int)((tt >> k) & 1));
        sT[l][tt] = mm;
    }
    if (t < 16) {
        float2 h = sAH[16 + (t & 1)];
        h = cmul(h, sAH[18 + ((t >> 1) & 1)]);
        h = cmul(h, sAH[20 + ((t >> 2) & 1)]);
        h = cmul(h, sAH[22 + ((t >> 3) & 1)]);
        sAH[24 + t] = h;
    }
    __syncthreads();

    unsigned xC = (unsigned)t ^ (((unsigned)t >> 4) & 15u);
    unsigned xA = ((unsigned)t << 4) ^ ((unsigned)t & 31u);
    unsigned xB = ((((unsigned)t >> 4) << 8) | ((unsigned)t & 15u)) ^ ((((unsigned)t >> 4) & 1u) << 4);

    // Product-state init -> config C positions
    {
        float2 tp = sAH[t & 1];
#pragma unroll
        for (int w = 1; w < 8; w++)
            tp = cmul(tp, sAH[2 * w + ((t >> w) & 1)]);
#pragma unroll
        for (int m = 0; m < 16; m++) {
            float2 a = cmul(tp, sAH[24 + m]);
            unsigned ad = ((unsigned)m << 8) ^ xC ^ (((unsigned)m & 1u) << 4);
            Sre[ad] = a.x; Sim[ad] = a.y;
        }
    }
    __syncthreads();

    u64 RE[8], IM[8];

#pragma unroll 1
    for (int l = 1; l <= 5; l++) {
        const u64* gl = sG + (l - 1) * 126;

        // ---- masked read into config A (fold CNOT ring of layer l-1) ----
        unsigned sb = sT[l - 1][t];
        unsigned r0 = sRM[(l - 1) * 12 + 0], r1 = sRM[(l - 1) * 12 + 1];
        unsigned r2 = sRM[(l - 1) * 12 + 2], r3 = sRM[(l - 1) * 12 + 3];
#pragma unroll
        for (int m = 0; m < 8; m++) {
            unsigned s0 = sb;
            if (m & 1) s0 ^= r0;
            if (m & 2) s0 ^= r1;
            if (m & 4) s0 ^= r2;
            unsigned s1 = s0 ^ r3;
            unsigned a0 = s0 ^ ((s0 >> 4) & 31u);
            unsigned a1 = s1 ^ ((s1 >> 4) & 31u);
            RE[m] = pk2(Sre[a0], Sre[a1]);
            IM[m] = pk2(Sim[a0], Sim[a1]);
        }
        bgate<0>(RE, IM, gl + 0);
        bgate<1>(RE, IM, gl + 12);
        bgate<2>(RE, IM, gl + 24);
        pgate(RE, IM, gl + 36);
        __syncthreads();
#pragma unroll
        for (int m = 0; m < 8; m++) {          // write A
            unsigned a0 = xA ^ (unsigned)m, a1 = a0 ^ 8u;
            float lo, hi;
            unpk(RE[m], lo, hi); Sre[a0] = lo; Sre[a1] = hi;
            unpk(IM[m], lo, hi); Sim[a0] = lo; Sim[a1] = hi;
        }
        __syncthreads();
#pragma unroll
        for (int m = 0; m < 8; m++) {          // read B
            unsigned a0 = xB ^ (unsigned)(m * 17), a1 = a0 ^ 136u;
            RE[m] = pk2(Sre[a0], Sre[a1]);
            IM[m] = pk2(Sim[a0], Sim[a1]);
        }
        bgate<0>(RE, IM, gl + 42);
        bgate<1>(RE, IM, gl + 54);
        bgate<2>(RE, IM, gl + 66);
        pgate(RE, IM, gl + 78);
#pragma unroll
        for (int m = 0; m < 8; m++) {          // write B (same per-thread set: no WAR sync)
            unsigned a0 = xB ^ (unsigned)(m * 17), a1 = a0 ^ 136u;
            float lo, hi;
            unpk(RE[m], lo, hi); Sre[a0] = lo; Sre[a1] = hi;
            unpk(IM[m], lo, hi); Sim[a0] = lo; Sim[a1] = hi;
        }
        __syncthreads();
#pragma unroll
        for (int m = 0; m < 8; m++) {          // read C
            unsigned a0 = xC ^ ((unsigned)m << 8) ^ (((unsigned)m & 1u) << 4);
            unsigned a1 = a0 ^ 2048u;
            RE[m] = pk2(Sre[a0], Sre[a1]);
            IM[m] = pk2(Sim[a0], Sim[a1]);
        }
        bgate<0>(RE, IM, gl + 84);
        bgate<1>(RE, IM, gl + 96);
        bgate<2>(RE, IM, gl + 108);
        pgate(RE, IM, gl + 120);
        if (l < 5) {
#pragma unroll
            for (int m = 0; m < 8; m++) {      // write C (same per-thread set)
                unsigned a0 = xC ^ ((unsigned)m << 8) ^ (((unsigned)m & 1u) << 4);
                unsigned a1 = a0 ^ 2048u;
                float lo, hi;
                unpk(RE[m], lo, hi); Sre[a0] = lo; Sre[a1] = hi;
                unpk(IM[m], lo, hi); Sim[a0] = lo; Sim[a1] = hi;
            }
            __syncthreads();
        }
    }

    // Expvals from config-C registers; layer-5 CNOT ring folded via inverse masks.
    {
        unsigned ptw = sT[5][t];
        unsigned q8 = sRM[68], q9 = sRM[69], q10 = sRM[70], q11 = sRM[71];
        float p[16];
#pragma unroll
        for (int m = 0; m < 8; m++) {
            u64 P = m2(RE[m], RE[m]);
            P = fma2(IM[m], IM[m], P);
            unpk(P, p[m], p[m + 8]);
        }
        float z[12];
#pragma unroll
        for (int w = 0; w < 12; w++) z[w] = 0.f;
#pragma unroll
        for (int m = 0; m < 16; m++) {
            unsigned sw = ptw;
            if (m & 1) sw ^= q8;
            if (m & 2) sw ^= q9;
            if (m & 4) sw ^= q10;
            if (m & 8) sw ^= q11;
#pragma unroll
            for (int w = 0; w < 12; w++)
                z[w] += ((sw >> w) & 1) ? -p[m] : p[m];
        }
#pragma unroll
        for (int w = 0; w < 12; w++) {
#pragma unroll
            for (int o = 16; o; o >>= 1)
                z[w] += __shfl_xor_sync(0xFFFFFFFFu, z[w], o);
        }
        __syncthreads();                 // all SMEM state reads done; reuse Sre
        if (lane == 0) {
#pragma unroll
            for (int w = 0; w < 12; w++) Sre[warp * 12 + w] = z[w];
        }
        __syncthreads();
        if (t < 12) {
            float sum = 0.f;
#pragma unroll
            for (int wp = 0; wp < 8; wp++) sum += Sre[wp * 12 + t];
            out[b * NQ + t] = sum;
        }
    }
}

// ---------------------------------------------------------------------------
extern "C" void kernel_launch(void* const* d_in, const int* in_sizes, int n_in,
                              void* d_out, int out_size) {
    const float* v = 0; const float* W = 0; const float* bc = 0; const float* wt = 0;
    for (int i = 0; i < n_in; i++) {
        if (in_sizes[i] == 4096 * 512)      v  = (const float*)d_in[i];
        else if (in_sizes[i] == 12 * 512)   W  = (const float*)d_in[i];
        else if (in_sizes[i] == 12)         bc = (const float*)d_in[i];
        else if (in_sizes[i] == 6 * 12 * 3) wt = (const float*)d_in[i];
    }
    float* out = (float*)d_out;

    precompute_kernel<<<1, 128>>>(wt);
    qvl_kernel<<<4096, THREADS>>>(v, W, bc, out);
}

// round 5
// speedup vs baseline: 1.8197x; 1.8197x over previous
#include <cuda_runtime.h>

#define NQ 12
#define THREADS 256
#define PI_F 3.14159265358979323846f
typedef unsigned long long u64;

// Staging (written by precompute kernel), then copied into __constant__
__device__ u64      g_G[630];
__device__ unsigned g_RM[72];
__device__ float2   g_U0[48];

__constant__ u64      cG[630];
__constant__ unsigned cRM[72];
__constant__ float2   cU0[48];

__device__ __forceinline__ float2 cmul(float2 a, float2 b) {
    return make_float2(a.x * b.x - a.y * b.y, a.x * b.y + a.y * b.x);
}
__device__ __forceinline__ u64 pk2(float a, float b) {
    u64 r; asm("mov.b64 %0,{%1,%2};" : "=l"(r) : "f"(a), "f"(b)); return r;
}
__device__ __forceinline__ void unpk(u64 x, float& a, float& b) {
    asm("mov.b64 {%0,%1},%2;" : "=f"(a), "=f"(b) : "l"(x));
}
__device__ __forceinline__ u64 m2(u64 a, u64 b) {
    u64 d; asm("mul.rn.f32x2 %0,%1,%2;" : "=l"(d) : "l"(a), "l"(b)); return d;
}
__device__ __forceinline__ u64 fma2(u64 a, u64 b, u64 c) {
    u64 d; asm("fma.rn.f32x2 %0,%1,%2,%3;" : "=l"(d) : "l"(a), "l"(b), "l"(c)); return d;
}
__device__ __forceinline__ u64 swp(u64 x) {
    float lo, hi; unpk(x, lo, hi); return pk2(hi, lo);
}

// ---------------------------------------------------------------------------
// Precompute kernel (identical to R3)
// ---------------------------------------------------------------------------
__global__ void precompute_kernel(const float* __restrict__ weights) {
    __shared__ float2 U[6][NQ][2][2];
    int tid = threadIdx.x;

    for (int g = tid; g < 6 * NQ; g += blockDim.x) {
        float phi = weights[g * 3 + 0];
        float th  = weights[g * 3 + 1];
        float om  = weights[g * 3 + 2];
        float s = sinf(0.5f * th), c = cosf(0.5f * th);
        float ap = 0.5f * (phi + om), am = 0.5f * (phi - om);
        float sap = sinf(ap), cap = cosf(ap);
        float sam = sinf(am), cam = cosf(am);
        int l = g / NQ, w = g % NQ;
        U[l][w][0][0] = make_float2(cap * c, -sap * c);
        U[l][w][0][1] = make_float2(-cam * s, -sam * s);
        U[l][w][1][0] = make_float2(cam * s, -sam * s);
        U[l][w][1][1] = make_float2(cap * c, sap * c);
    }
    __syncthreads();

    for (int e = tid; e < NQ * 4; e += blockDim.x) {
        int w = e >> 2;
        g_U0[e] = U[0][w][(e >> 1) & 1][e & 1];
    }
    if (tid < 15) {
        int l = tid / 3 + 1, c = tid % 3;
        int base = (l - 1) * 126 + c * 42;
        for (int bit = 0; bit < 3; bit++) {
            for (int e = 0; e < 4; e++) {
                float2 u = U[l][c * 4 + bit][e >> 1][e & 1];
                int off = base + bit * 12 + e * 3;
                g_G[off + 0] = pk2(u.x, u.x);
                g_G[off + 1] = pk2(-u.y, -u.y);
                g_G[off + 2] = pk2(u.y, u.y);
            }
        }
        float2 u00 = U[l][c * 4 + 3][0][0], u01 = U[l][c * 4 + 3][0][1];
        float2 u10 = U[l][c * 4 + 3][1][0], u11 = U[l][c * 4 + 3][1][1];
        g_G[base + 36] = pk2(u00.x, u11.x);
        g_G[base + 37] = pk2(u01.x, u10.x);
        g_G[base + 38] = pk2(-u00.y, -u11.y);
        g_G[base + 39] = pk2(-u01.y, -u10.y);
        g_G[base + 40] = pk2(u00.y, u11.y);
        g_G[base + 41] = pk2(u01.y, u10.y);
    }
    for (int e = tid; e < 6 * NQ; e += blockDim.x) {
        int l = e / NQ, bb = e % NQ;
        unsigned i = 1u << bb;
        if (l < 5) {
            int r = (l % (NQ - 1)) + 1;
            for (int w = NQ - 1; w >= 0; --w)
                i ^= ((i >> w) & 1u) << ((w + r) % NQ);
        } else {
            int r = (5 % (NQ - 1)) + 1;
            for (int w = 0; w < NQ; ++w)
                i ^= ((i >> w) & 1u) << ((w + r) % NQ);
        }
        g_RM[l * NQ + bb] = i;
    }
}

// ---------------------------------------------------------------------------
// Gates on SoA packed registers (RE[m],IM[m] pack amp pair (m, m+8))
// ---------------------------------------------------------------------------
template <int Q>
__device__ __forceinline__ void bgate(u64* RE, u64* IM, const u64* __restrict__ g) {
    u64 c00r = g[0], c00n = g[1], c00p = g[2];
    u64 c01r = g[3], c01n = g[4], c01p = g[5];
    u64 c10r = g[6], c10n = g[7], c10p = g[8];
    u64 c11r = g[9], c11n = g[10], c11p = g[11];
#pragma unroll
    for (int h = 0; h < 4; h++) {
        const int a = ((h >> Q) << (Q + 1)) | (h & ((1 << Q) - 1));
        const int bq = a + (1 << Q);
        u64 x0r = RE[a], x0i = IM[a], x1r = RE[bq], x1i = IM[bq];
        u64 y0r = m2(c00r, x0r); y0r = fma2(c00n, x0i, y0r); y0r = fma2(c01r, x1r, y0r); y0r = fma2(c01n, x1i, y0r);
        u64 y0i = m2(c00r, x0i); y0i = fma2(c00p, x0r, y0i); y0i = fma2(c01r, x1i, y0i); y0i = fma2(c01p, x1r, y0i);
        u64 y1r = m2(c10r, x0r); y1r = fma2(c10n, x0i, y1r); y1r = fma2(c11r, x1r, y1r); y1r = fma2(c11n, x1i, y1r);
        u64 y1i = m2(c10r, x0i); y1i = fma2(c10p, x0r, y1i); y1i = fma2(c11r, x1i, y1i); y1i = fma2(c11p, x1r, y1i);
        RE[a] = y0r; IM[a] = y0i; RE[bq] = y1r; IM[bq] = y1i;
    }
}

__device__ __forceinline__ void pgate(u64* RE, u64* IM, const u64* __restrict__ g) {
    u64 P1 = g[0], P2 = g[1], P3 = g[2], P4 = g[3], Q3 = g[4], Q4 = g[5];
#pragma unroll
    for (int m = 0; m < 8; m++) {
        u64 xr = RE[m], xi = IM[m];
        u64 sr = swp(xr), si = swp(xi);
        u64 yr = m2(P1, xr); yr = fma2(P2, sr, yr); yr = fma2(P3, xi, yr); yr = fma2(P4, si, yr);
        u64 yi = m2(P1, xi); yi = fma2(P2, si, yi); yi = fma2(Q3, xr, yi); yi = fma2(Q4, sr, yi);
        RE[m] = yr; IM[m] = yi;
    }
}

// ---------------------------------------------------------------------------
// Main kernel. SMEM SoA, swizzle phi(j) = j ^ ((j>>4)&31).
// Config A: j=(t<<4)|m  Config B: j=(thi<<8)|(m<<4)|tlo  Config C: j=(m<<8)|t
// ---------------------------------------------------------------------------
__global__ void __launch_bounds__(THREADS, 4) qvl_kernel(
    const float* __restrict__ v, const float* __restrict__ W,
    const float* __restrict__ bc, float* __restrict__ out) {
    __shared__ float  SS[8192];        // [0..4095]=re, [4096..8191]=im; reused at tail
    __shared__ float2 sAH[40];         // [0..23] per-qubit 2-vecs, [24..39] high product
    __shared__ int    sWtab[12];       // expval: 4-bit WHT index per output wire
#define SRE(i) SS[(i)]
#define SIM(i) SS[4096 + (i)]

    int b = blockIdx.x, t = threadIdx.x;
    int lane = t & 31, warp = t >> 5;

    // expval index table (once per CTA)
    if (t < 12) {
        unsigned w = t;
        int s = (int)(((cRM[68] >> w) & 1u) | (((cRM[69] >> w) & 1u) << 1)
                    | (((cRM[70] >> w) & 1u) << 2) | (((cRM[71] >> w) & 1u) << 3));
        sWtab[t] = s;
    }

    // Angles: x_w = tanh(v[b]·W[w] + b[w]) * pi, fold layer-0 Rot
    const float* vrow = v + (size_t)b * 512;
    for (int w = warp; w < NQ; w += 8) {
        const float* Wr = W + w * 512;
        float acc = 0.f;
#pragma unroll
        for (int q = 0; q < 16; q++)
            acc = fmaf(vrow[lane + 32 * q], Wr[lane + 32 * q], acc);
#pragma unroll
        for (int o = 16; o; o >>= 1) acc += __shfl_xor_sync(0xFFFFFFFFu, acc, o);
        if (lane == 0) {
            float x = tanhf(acc + bc[w]) * PI_F;
            float ch = cosf(0.5f * x), sh = sinf(0.5f * x);
            float2 u00 = cU0[w * 4 + 0], u01 = cU0[w * 4 + 1];
            float2 u10 = cU0[w * 4 + 2], u11 = cU0[w * 4 + 3];
            sAH[2 * w + 0] = make_float2(u00.x * ch + u01.x * sh, u00.y * ch + u01.y * sh);
            sAH[2 * w + 1] = make_float2(u10.x * ch + u11.x * sh, u10.y * ch + u11.y * sh);
        }
    }
    __syncthreads();
    if (t < 16) {
        float2 h = sAH[16 + (t & 1)];
        h = cmul(h, sAH[18 + ((t >> 1) & 1)]);
        h = cmul(h, sAH[20 + ((t >> 2) & 1)]);
        h = cmul(h, sAH[22 + ((t >> 3) & 1)]);
        sAH[24 + t] = h;
    }
    __syncthreads();

    unsigned xC = (unsigned)t ^ (((unsigned)t >> 4) & 15u);
    unsigned xA = ((unsigned)t << 4) ^ ((unsigned)t & 31u);
    unsigned xB = ((((unsigned)t >> 4) << 8) | ((unsigned)t & 15u)) ^ ((((unsigned)t >> 4) & 1u) << 4);

    // Product-state init -> config C positions
    {
        float2 tp = sAH[t & 1];
#pragma unroll
        for (int w = 1; w < 8; w++)
            tp = cmul(tp, sAH[2 * w + ((t >> w) & 1)]);
#pragma unroll
        for (int m = 0; m < 16; m++) {
            float2 a = cmul(tp, sAH[24 + m]);
            unsigned ad = ((unsigned)m << 8) ^ xC ^ (((unsigned)m & 1u) << 4);
            SRE(ad) = a.x; SIM(ad) = a.y;
        }
    }
    __syncthreads();

    u64 RE[8], IM[8];

#pragma unroll 1
    for (int l = 1; l <= 5; l++) {
        const u64* gl = cG + (l - 1) * 126;
        const unsigned* rm = cRM + (l - 1) * 12;

        // ---- masked read into config A (CNOT ring of layer l-1 folded) ----
        // Swizzle is GF(2)-linear: pre-swizzle the masks, not the addresses.
        unsigned sb = 0;
#pragma unroll
        for (int k = 0; k < 8; k++)
            sb ^= rm[4 + k] & (unsigned)(-(int)((t >> k) & 1));
        unsigned sbz = sb ^ ((sb >> 4) & 31u);
        unsigned r0 = rm[0], r1 = rm[1], r2 = rm[2], r3 = rm[3];
        unsigned z0 = r0 ^ ((r0 >> 4) & 31u);
        unsigned z1 = r1 ^ ((r1 >> 4) & 31u);
        unsigned z2 = r2 ^ ((r2 >> 4) & 31u);
        unsigned z3 = r3 ^ ((r3 >> 4) & 31u);
#pragma unroll
        for (int m = 0; m < 8; m++) {
            unsigned a0 = sbz;
            if (m & 1) a0 ^= z0;
            if (m & 2) a0 ^= z1;
            if (m & 4) a0 ^= z2;
            unsigned a1 = a0 ^ z3;
            RE[m] = pk2(SRE(a0), SRE(a1));
            IM[m] = pk2(SIM(a0), SIM(a1));
        }
        bgate<0>(RE, IM, gl + 0);
        bgate<1>(RE, IM, gl + 12);
        bgate<2>(RE, IM, gl + 24);
        pgate(RE, IM, gl + 36);
        __syncthreads();                       // all masked reads done before write A
#pragma unroll
        for (int m = 0; m < 8; m++) {          // write A
            unsigned a0 = xA ^ (unsigned)m, a1 = a0 ^ 8u;
            float lo, hi;
            unpk(RE[m], lo, hi); SRE(a0) = lo; SRE(a1) = hi;
            unpk(IM[m], lo, hi); SIM(a0) = lo; SIM(a1) = hi;
        }
        __syncwarp();                          // A<->B exchange is within 16-thread groups
#pragma unroll
        for (int m = 0; m < 8; m++) {          // read B
            unsigned a0 = xB ^ (unsigned)(m * 17), a1 = a0 ^ 136u;
            RE[m] = pk2(SRE(a0), SRE(a1));
            IM[m] = pk2(SIM(a0), SIM(a1));
        }
        bgate<0>(RE, IM, gl + 42);
        bgate<1>(RE, IM, gl + 54);
        bgate<2>(RE, IM, gl + 66);
        pgate(RE, IM, gl + 78);
#pragma unroll
        for (int m = 0; m < 8; m++) {          // write B (same per-thread set: no WAR sync)
            unsigned a0 = xB ^ (unsigned)(m * 17), a1 = a0 ^ 136u;
            float lo, hi;
            unpk(RE[m], lo, hi); SRE(a0) = lo; SRE(a1) = hi;
            unpk(IM[m], lo, hi); SIM(a0) = lo; SIM(a1) = hi;
        }
        __syncthreads();                       // B->C crosses the whole CTA
#pragma unroll
        for (int m = 0; m < 8; m++) {          // read C
            unsigned a0 = xC ^ ((unsigned)m << 8) ^ (((unsigned)m & 1u) << 4);
            unsigned a1 = a0 ^ 2048u;
            RE[m] = pk2(SRE(a0), SRE(a1));
            IM[m] = pk2(SIM(a0), SIM(a1));
        }
        bgate<0>(RE, IM, gl + 84);
        bgate<1>(RE, IM, gl + 96);
        bgate<2>(RE, IM, gl + 108);
        pgate(RE, IM, gl + 120);
        if (l < 5) {
#pragma unroll
            for (int m = 0; m < 8; m++) {      // write C (same per-thread set)
                unsigned a0 = xC ^ ((unsigned)m << 8) ^ (((unsigned)m & 1u) << 4);
                unsigned a1 = a0 ^ 2048u;
                float lo, hi;
                unpk(RE[m], lo, hi); SRE(a0) = lo; SRE(a1) = hi;
                unpk(IM[m], lo, hi); SIM(a0) = lo; SIM(a1) = hi;
            }
            __syncthreads();
        }
    }

    // ---- Expvals via 4-level Walsh transform over the m-bits ----
    // z[w] = (-1)^{bit_w(ptw)} * T[s_w],  T = WHT_m(p),  s_w from inverse-ring masks.
    {
        const unsigned* ri = cRM + 60;
        unsigned ptw = 0;
#pragma unroll
        for (int k = 0; k < 8; k++)
            ptw ^= ri[k] & (unsigned)(-(int)((t >> k) & 1));

        float p[16];
#pragma unroll
        for (int m = 0; m < 8; m++) {
            u64 P = m2(RE[m], RE[m]);
            P = fma2(IM[m], IM[m], P);
            unpk(P, p[m], p[m + 8]);
        }
        // WHT in place (bit0<->q8, bit1<->q9, bit2<->q10, bit3<->q11)
#pragma unroll
        for (int st = 1; st < 16; st <<= 1) {
#pragma unroll
            for (int i = 0; i < 16; i++) {
                if (!(i & st)) {
                    float a = p[i], bb2 = p[i | st];
                    p[i] = a + bb2;
                    p[i | st] = a - bb2;
                }
            }
        }
        __syncthreads();                 // all state reads complete; reuse SS
        // Store T row (stride 17: conflict-free), then dynamic-index pickup.
#pragma unroll
        for (int s = 0; s < 16; s++) SS[t * 17 + s] = p[s];
        float z[12];
#pragma unroll
        for (int w = 0; w < 12; w++) {
            float val = SS[t * 17 + sWtab[w]];
            z[w] = ((ptw >> w) & 1u) ? -val : val;
        }
#pragma unroll
        for (int w = 0; w < 12; w++) {
#pragma unroll
            for (int o = 16; o; o >>= 1)
                z[w] += __shfl_xor_sync(0xFFFFFFFFu, z[w], o);
        }
        if (lane == 0) {
#pragma unroll
            for (int w = 0; w < 12; w++) SS[4400 + warp * 12 + w] = z[w];
        }
        __syncthreads();
        if (t < 12) {
            float sum = 0.f;
#pragma unroll
            for (int wp = 0; wp < 8; wp++) sum += SS[4400 + wp * 12 + t];
            out[b * NQ + t] = sum;
        }
    }
#undef SRE
#undef SIM
}

// ---------------------------------------------------------------------------
extern "C" void kernel_launch(void* const* d_in, const int* in_sizes, int n_in,
                              void* d_out, int out_size) {
    const float* v = 0; const float* W = 0; const float* bc = 0; const float* wt = 0;
    for (int i = 0; i < n_in; i++) {
        if (in_sizes[i] == 4096 * 512)      v  = (const float*)d_in[i];
        else if (in_sizes[i] == 12 * 512)   W  = (const float*)d_in[i];
        else if (in_sizes[i] == 12)         bc = (const float*)d_in[i];
        else if (in_sizes[i] == 6 * 12 * 3) wt = (const float*)d_in[i];
    }
    float* out = (float*)d_out;

    precompute_kernel<<<1, 128>>>(wt);

    void *pG = 0, *pRM = 0, *pU0 = 0;
    cudaGetSymbolAddress(&pG, g_G);
    cudaGetSymbolAddress(&pRM, g_RM);
    cudaGetSymbolAddress(&pU0, g_U0);
    cudaMemcpyToSymbolAsync(cG,  pG,  sizeof(g_G),  0, cudaMemcpyDeviceToDevice, 0);
    cudaMemcpyToSymbolAsync(cRM, pRM, sizeof(g_RM), 0, cudaMemcpyDeviceToDevice, 0);
    cudaMemcpyToSymbolAsync(cU0, pU0, sizeof(g_U0), 0, cudaMemcpyDeviceToDevice, 0);

    qvl_kernel<<<4096, THREADS>>>(v, W, bc, out);
}